// round 1
// baseline (speedup 1.0000x reference)
#include <cuda_runtime.h>

#define B_ 2
#define T_ 2048
#define D_ 1024
#define H_ 16
#define DK_ 64
#define M_ (B_*T_)           // 4096 rows
#define SCALE_ 0.125f        // 1/sqrt(64)

// ---------------- scratch (device globals; no allocations allowed) ----------
__device__ float g_Q[M_*D_];
__device__ float g_K[M_*D_];
__device__ float g_V[M_*D_];
__device__ float g_CTX[M_*D_];
__device__ float g_bias[M_];
__device__ int   g_maskmode;   // 0=int32, 1=float32, 2=uint8

// ---------------- mask dtype detection ----------------
// Scan the first 4096 bytes (safe for every candidate encoding of the
// [B*T]=4096-element bool mask) and classify deterministically.
__global__ void detect_mask_kernel(const unsigned int* __restrict__ w) {
    __shared__ int s_badint, s_badfloat;
    if (threadIdx.x == 0) { s_badint = 0; s_badfloat = 0; }
    __syncthreads();
    int bi = 0, bf = 0;
    for (int i = threadIdx.x; i < 1024; i += blockDim.x) {
        unsigned v = w[i];
        if (v > 1u) bi = 1;                               // not {0,1} int32
        if (v != 0u && v != 0x3F800000u) bf = 1;          // not {0.0f,1.0f}
    }
    if (bi) atomicOr(&s_badint, 1);
    if (bf) atomicOr(&s_badfloat, 1);
    __syncthreads();
    if (threadIdx.x == 0)
        g_maskmode = (!s_badint) ? 0 : ((!s_badfloat) ? 1 : 2);
}

__global__ void build_bias_kernel(const void* __restrict__ mask) {
    int i = blockIdx.x * blockDim.x + threadIdx.x;
    if (i >= M_) return;
    int mode = g_maskmode;
    bool keep;
    if (mode == 0)      keep = ((const int*)mask)[i] != 0;
    else if (mode == 1) keep = ((const float*)mask)[i] != 0.0f;
    else                keep = ((const unsigned char*)mask)[i] != 0;
    g_bias[i] = keep ? 0.0f : -1e30f;
}

// ---------------- GEMM: C[M,N] = A[M,K] @ W[N,K]^T + b[N] ----------------
// 64x64 tile, K-step 16, 256 threads, 4x4 microtile. Shared stored
// k-major-transposed with +4 pad for conflict-free float4 reads.
__global__ __launch_bounds__(256) void gemm_bias_kernel(
    const float* __restrict__ A, const float* __restrict__ W,
    const float* __restrict__ bvec, float* __restrict__ C,
    int Mdim, int Ndim, int Kdim)
{
    __shared__ float As[16][68];
    __shared__ float Ws[16][68];
    const int tid = threadIdx.x;
    const int tx = tid & 15, ty = tid >> 4;
    const int m0 = blockIdx.y * 64, n0 = blockIdx.x * 64;
    const int lr = tid >> 2;          // 0..63 tile row
    const int lc = (tid & 3) * 4;     // 0,4,8,12 k-offset
    const float* Ap = A + (size_t)(m0 + lr) * Kdim + lc;
    const float* Wp = W + (size_t)(n0 + lr) * Kdim + lc;

    float acc[4][4];
#pragma unroll
    for (int i = 0; i < 4; i++)
#pragma unroll
        for (int j = 0; j < 4; j++) acc[i][j] = 0.f;

    for (int k0 = 0; k0 < Kdim; k0 += 16) {
        float4 av = *(const float4*)(Ap + k0);
        float4 wv = *(const float4*)(Wp + k0);
        __syncthreads();   // previous tile fully consumed
        As[lc + 0][lr] = av.x; As[lc + 1][lr] = av.y;
        As[lc + 2][lr] = av.z; As[lc + 3][lr] = av.w;
        Ws[lc + 0][lr] = wv.x; Ws[lc + 1][lr] = wv.y;
        Ws[lc + 2][lr] = wv.z; Ws[lc + 3][lr] = wv.w;
        __syncthreads();
#pragma unroll
        for (int k = 0; k < 16; k++) {
            float4 a = *(const float4*)&As[k][ty * 4];
            float4 w = *(const float4*)&Ws[k][tx * 4];
            acc[0][0] += a.x * w.x; acc[0][1] += a.x * w.y; acc[0][2] += a.x * w.z; acc[0][3] += a.x * w.w;
            acc[1][0] += a.y * w.x; acc[1][1] += a.y * w.y; acc[1][2] += a.y * w.z; acc[1][3] += a.y * w.w;
            acc[2][0] += a.z * w.x; acc[2][1] += a.z * w.y; acc[2][2] += a.z * w.z; acc[2][3] += a.z * w.w;
            acc[3][0] += a.w * w.x; acc[3][1] += a.w * w.y; acc[3][2] += a.w * w.z; acc[3][3] += a.w * w.w;
        }
    }

    float4 bb = *(const float4*)(bvec + n0 + tx * 4);
#pragma unroll
    for (int i = 0; i < 4; i++) {
        float4 o;
        o.x = acc[i][0] + bb.x; o.y = acc[i][1] + bb.y;
        o.z = acc[i][2] + bb.z; o.w = acc[i][3] + bb.w;
        *(float4*)&C[(size_t)(m0 + ty * 4 + i) * Ndim + n0 + tx * 4] = o;
    }
}

// ---------------- attention: flash-style, 1 query row per thread ----------
// Block = 128 threads = 128 query rows of one (b,h). S-tiles of 16 in shared.
// All K/V shared reads are uniform broadcasts -> FFMA-issue bound.
__global__ __launch_bounds__(128) void attn_kernel(
    const float* __restrict__ Q, const float* __restrict__ Kg,
    const float* __restrict__ Vg, float* __restrict__ CTX)
{
    __shared__ float4 Ks[16 * 16];
    __shared__ float4 Vs[16 * 16];
    __shared__ float  Bs[16];
    const int b = blockIdx.z, h = blockIdx.y;
    const int t = blockIdx.x * 128 + threadIdx.x;
    const size_t qoff = ((size_t)(b * T_ + t)) * D_ + h * DK_;

    float4 q[16], o[16];
#pragma unroll
    for (int c = 0; c < 16; c++) {
        q[c] = *(const float4*)(Q + qoff + 4 * c);
        o[c] = make_float4(0.f, 0.f, 0.f, 0.f);
    }
    float mx = -1e30f, l = 0.f;

    const float* kb = Kg + ((size_t)b * T_) * D_ + h * DK_;
    const float* vb = Vg + ((size_t)b * T_) * D_ + h * DK_;
    const float* biasb = g_bias + b * T_;

    for (int s0 = 0; s0 < T_; s0 += 16) {
        __syncthreads();
        {
            int idx = threadIdx.x;                  // 0..127
            int r = idx >> 4, c = idx & 15;
            Ks[idx] = *(const float4*)(kb + (size_t)(s0 + r) * D_ + 4 * c);
            Vs[idx] = *(const float4*)(vb + (size_t)(s0 + r) * D_ + 4 * c);
            int idx2 = idx + 128;
            int r2 = idx2 >> 4, c2 = idx2 & 15;
            Ks[idx2] = *(const float4*)(kb + (size_t)(s0 + r2) * D_ + 4 * c2);
            Vs[idx2] = *(const float4*)(vb + (size_t)(s0 + r2) * D_ + 4 * c2);
            if (idx < 16) Bs[idx] = biasb[s0 + idx];
        }
        __syncthreads();

        float sv[16];
#pragma unroll
        for (int j = 0; j < 16; j++) {
            float p0 = 0.f, p1 = 0.f, p2 = 0.f, p3 = 0.f;
#pragma unroll
            for (int c = 0; c < 16; c++) {
                float4 kv = Ks[j * 16 + c];
                float4 qq = q[c];
                p0 += qq.x * kv.x; p1 += qq.y * kv.y;
                p2 += qq.z * kv.z; p3 += qq.w * kv.w;
            }
            sv[j] = ((p0 + p1) + (p2 + p3)) * SCALE_ + Bs[j];
        }

        float nm = mx;
#pragma unroll
        for (int j = 0; j < 16; j++) nm = fmaxf(nm, sv[j]);
        float corr = __expf(mx - nm);
        mx = nm;
        l *= corr;
#pragma unroll
        for (int c = 0; c < 16; c++) {
            o[c].x *= corr; o[c].y *= corr; o[c].z *= corr; o[c].w *= corr;
        }
#pragma unroll
        for (int j = 0; j < 16; j++) {
            float p = __expf(sv[j] - nm);
            l += p;
#pragma unroll
            for (int c = 0; c < 16; c++) {
                float4 vv = Vs[j * 16 + c];
                o[c].x += p * vv.x; o[c].y += p * vv.y;
                o[c].z += p * vv.z; o[c].w += p * vv.w;
            }
        }
    }

    float inv = 1.f / l;
    float* op = CTX + qoff;
#pragma unroll
    for (int c = 0; c < 16; c++) {
        float4 ov = make_float4(o[c].x * inv, o[c].y * inv,
                                o[c].z * inv, o[c].w * inv);
        *(float4*)(op + 4 * c) = ov;
    }
}

// ---------------- launch ----------------
extern "C" void kernel_launch(void* const* d_in, const int* in_sizes, int n_in,
                              void* d_out, int out_size)
{
    const float* query = (const float*)d_in[0];
    const float* key   = (const float*)d_in[1];
    const float* value = (const float*)d_in[2];
    const void*  mask  = d_in[3];
    const float* Wq = (const float*)d_in[4];  const float* bq = (const float*)d_in[5];
    const float* Wk = (const float*)d_in[6];  const float* bk = (const float*)d_in[7];
    const float* Wv = (const float*)d_in[8];  const float* bv = (const float*)d_in[9];
    const float* Wo = (const float*)d_in[10]; const float* bo = (const float*)d_in[11];

    float *Qb, *Kb, *Vb, *Cb;
    cudaGetSymbolAddress((void**)&Qb, g_Q);
    cudaGetSymbolAddress((void**)&Kb, g_K);
    cudaGetSymbolAddress((void**)&Vb, g_V);
    cudaGetSymbolAddress((void**)&Cb, g_CTX);

    detect_mask_kernel<<<1, 256>>>((const unsigned int*)mask);
    build_bias_kernel<<<(M_ + 255) / 256, 256>>>(mask);

    dim3 gg(D_ / 64, M_ / 64);   // (16, 64)
    gemm_bias_kernel<<<gg, 256>>>(query, Wq, bq, Qb, M_, D_, D_);
    gemm_bias_kernel<<<gg, 256>>>(key,   Wk, bk, Kb, M_, D_, D_);
    gemm_bias_kernel<<<gg, 256>>>(value, Wv, bv, Vb, M_, D_, D_);

    attn_kernel<<<dim3(T_ / 128, H_, B_), 128>>>(Qb, Kb, Vb, Cb);

    gemm_bias_kernel<<<gg, 256>>>(Cb, Wo, bo, (float*)d_out, M_, D_, D_);
}

// round 2
// speedup vs baseline: 1.1681x; 1.1681x over previous
#include <cuda_runtime.h>
#include <cstdint>

#define B_ 2
#define T_ 2048
#define D_ 1024
#define H_ 16
#define DK_ 64
#define M_ (B_*T_)           // 4096 rows
#define SCALE_ 0.125f        // 1/sqrt(64)

// ---------------- scratch (device globals; no allocations allowed) ----------
__device__ float g_Q[M_*D_];
__device__ float g_K[M_*D_];
__device__ float g_V[M_*D_];
__device__ float g_CTX[M_*D_];
__device__ float g_bias[M_];
__device__ int   g_maskmode;   // 0=int32, 1=float32, 2=uint8

// ---------------- mask dtype detection ----------------
__global__ void detect_mask_kernel(const unsigned int* __restrict__ w) {
    __shared__ int s_badint, s_badfloat;
    if (threadIdx.x == 0) { s_badint = 0; s_badfloat = 0; }
    __syncthreads();
    int bi = 0, bf = 0;
    for (int i = threadIdx.x; i < 1024; i += blockDim.x) {
        unsigned v = w[i];
        if (v > 1u) bi = 1;                               // not {0,1} int32
        if (v != 0u && v != 0x3F800000u) bf = 1;          // not {0.0f,1.0f}
    }
    if (bi) atomicOr(&s_badint, 1);
    if (bf) atomicOr(&s_badfloat, 1);
    __syncthreads();
    if (threadIdx.x == 0)
        g_maskmode = (!s_badint) ? 0 : ((!s_badfloat) ? 1 : 2);
}

__global__ void build_bias_kernel(const void* __restrict__ mask) {
    int i = blockIdx.x * blockDim.x + threadIdx.x;
    if (i >= M_) return;
    int mode = g_maskmode;
    bool keep;
    if (mode == 0)      keep = ((const int*)mask)[i] != 0;
    else if (mode == 1) keep = ((const float*)mask)[i] != 0.0f;
    else                keep = ((const unsigned char*)mask)[i] != 0;
    g_bias[i] = keep ? 0.0f : -1e30f;
}

// ================= tf32x3 tensor-core GEMM ==================
// C[M,N] = A[M,K] @ W[N,K]^T + b[N], M=4096 N=1024 K=1024.
// mma.sync.m16n8k8.tf32 with hi/lo split: a = ah + al (ah = mantissa-masked),
// D += Ah*Bh + Al*Bh + Ah*Bl  -> ~fp32 accuracy.
// Block tile 64(M) x 128(N), 8 warps (2m x 4n), warp tile 32x32, K-step 16,
// double-buffered smem, stride-20 pad (conflict-free fragment loads).

#define TSTRIDE 20

__device__ __forceinline__ void mma_tf32(float* d, const uint32_t* a, const uint32_t* b) {
    asm volatile(
        "mma.sync.aligned.m16n8k8.row.col.f32.tf32.tf32.f32 "
        "{%0,%1,%2,%3}, {%4,%5,%6,%7}, {%8,%9}, {%0,%1,%2,%3};"
        : "+f"(d[0]), "+f"(d[1]), "+f"(d[2]), "+f"(d[3])
        : "r"(a[0]), "r"(a[1]), "r"(a[2]), "r"(a[3]), "r"(b[0]), "r"(b[1]));
}

__device__ __forceinline__ void split_tf32(float x, uint32_t& hi, uint32_t& lo) {
    uint32_t h = __float_as_uint(x) & 0xFFFFE000u;   // keep tf32 bits
    hi = h;
    lo = __float_as_uint(x - __uint_as_float(h));    // exact residual
}

__global__ __launch_bounds__(256) void gemm_tf32x3_kernel(
    const float* __restrict__ A, const float* __restrict__ W,
    const float* __restrict__ bvec, float* __restrict__ C)
{
    __shared__ float As[2][64 * TSTRIDE];
    __shared__ float Bs[2][128 * TSTRIDE];

    const int tid  = threadIdx.x;
    const int lane = tid & 31;
    const int wid  = tid >> 5;
    const int wm   = (wid >> 2) * 32;    // warp m offset: 0 / 32
    const int wn   = (wid & 3) * 32;     // warp n offset: 0..96
    const int gid  = lane >> 2;          // groupID (0..7)
    const int tig  = lane & 3;           // threadID in group

    const int m0 = blockIdx.y * 64;
    const int n0 = blockIdx.x * 128;

    float acc[2][4][4];
#pragma unroll
    for (int mt = 0; mt < 2; mt++)
#pragma unroll
        for (int nt = 0; nt < 4; nt++)
#pragma unroll
            for (int i = 0; i < 4; i++) acc[mt][nt][i] = 0.f;

    // fill mapping
    const int arow = tid >> 2;           // 0..63
    const int acg  = (tid & 3) * 4;      // 0,4,8,12
    const float* Ag  = A + (size_t)(m0 + arow) * 1024 + acg;
    const float* Wg0 = W + (size_t)(n0 + arow) * 1024 + acg;
    const float* Wg1 = W + (size_t)(n0 + arow + 64) * 1024 + acg;

    float4 pa, pb0, pb1;
    pa  = *(const float4*)(Ag);
    pb0 = *(const float4*)(Wg0);
    pb1 = *(const float4*)(Wg1);

#define GEMM_STORE(BUF)                                                     \
    do {                                                                    \
        *(float4*)&As[BUF][arow * TSTRIDE + acg]        = pa;               \
        *(float4*)&Bs[BUF][arow * TSTRIDE + acg]        = pb0;              \
        *(float4*)&Bs[BUF][(arow + 64) * TSTRIDE + acg] = pb1;              \
    } while (0)

#define GEMM_COMPUTE(BUF)                                                   \
    do {                                                                    \
        _Pragma("unroll")                                                   \
        for (int kc = 0; kc < 2; kc++) {                                    \
            const int kb = kc * 8;                                          \
            uint32_t Ah[2][4], Al[2][4], Bh[4][2], Bl[4][2];                \
            _Pragma("unroll")                                               \
            for (int mt = 0; mt < 2; mt++) {                                \
                const float* ap = &As[BUF][(wm + mt * 16 + gid) * TSTRIDE + kb + tig]; \
                float x0 = ap[0];                                           \
                float x1 = ap[8 * TSTRIDE];                                 \
                float x2 = ap[4];                                           \
                float x3 = ap[8 * TSTRIDE + 4];                             \
                split_tf32(x0, Ah[mt][0], Al[mt][0]);                       \
                split_tf32(x1, Ah[mt][1], Al[mt][1]);                       \
                split_tf32(x2, Ah[mt][2], Al[mt][2]);                       \
                split_tf32(x3, Ah[mt][3], Al[mt][3]);                       \
            }                                                               \
            _Pragma("unroll")                                               \
            for (int nt = 0; nt < 4; nt++) {                                \
                const float* bp = &Bs[BUF][(wn + nt * 8 + gid) * TSTRIDE + kb + tig]; \
                float y0 = bp[0];                                           \
                float y1 = bp[4];                                           \
                split_tf32(y0, Bh[nt][0], Bl[nt][0]);                       \
                split_tf32(y1, Bh[nt][1], Bl[nt][1]);                       \
            }                                                               \
            _Pragma("unroll")                                               \
            for (int mt = 0; mt < 2; mt++)                                  \
                _Pragma("unroll")                                           \
                for (int nt = 0; nt < 4; nt++) {                            \
                    mma_tf32(acc[mt][nt], Ah[mt], Bh[nt]);                  \
                    mma_tf32(acc[mt][nt], Al[mt], Bh[nt]);                  \
                    mma_tf32(acc[mt][nt], Ah[mt], Bl[nt]);                  \
                }                                                           \
        }                                                                   \
    } while (0)

    GEMM_STORE(0);
    __syncthreads();

    int buf = 0;
    for (int k0 = 16; k0 < 1024; k0 += 16) {
        pa  = *(const float4*)(Ag + k0);
        pb0 = *(const float4*)(Wg0 + k0);
        pb1 = *(const float4*)(Wg1 + k0);
        if (buf == 0) GEMM_COMPUTE(0); else GEMM_COMPUTE(1);
        __syncthreads();
        if (buf == 0) GEMM_STORE(1); else GEMM_STORE(0);
        __syncthreads();
        buf ^= 1;
    }
    if (buf == 0) GEMM_COMPUTE(0); else GEMM_COMPUTE(1);

    // epilogue: bias + store
#pragma unroll
    for (int mt = 0; mt < 2; mt++) {
#pragma unroll
        for (int nt = 0; nt < 4; nt++) {
            int gm = m0 + wm + mt * 16 + gid;
            int gn = n0 + wn + nt * 8 + tig * 2;
            float b0 = __ldg(bvec + gn);
            float b1 = __ldg(bvec + gn + 1);
            *(float2*)&C[(size_t)gm * 1024 + gn] =
                make_float2(acc[mt][nt][0] + b0, acc[mt][nt][1] + b1);
            *(float2*)&C[(size_t)(gm + 8) * 1024 + gn] =
                make_float2(acc[mt][nt][2] + b0, acc[mt][nt][3] + b1);
        }
    }
}

// ---------------- attention: flash-style, 1 query row per thread ----------
__global__ __launch_bounds__(128) void attn_kernel(
    const float* __restrict__ Q, const float* __restrict__ Kg,
    const float* __restrict__ Vg, float* __restrict__ CTX)
{
    __shared__ float4 Ks[16 * 16];
    __shared__ float4 Vs[16 * 16];
    __shared__ float  Bs[16];
    const int b = blockIdx.z, h = blockIdx.y;
    const int t = blockIdx.x * 128 + threadIdx.x;
    const size_t qoff = ((size_t)(b * T_ + t)) * D_ + h * DK_;

    float4 q[16], o[16];
#pragma unroll
    for (int c = 0; c < 16; c++) {
        q[c] = *(const float4*)(Q + qoff + 4 * c);
        o[c] = make_float4(0.f, 0.f, 0.f, 0.f);
    }
    float mx = -1e30f, l = 0.f;

    const float* kb = Kg + ((size_t)b * T_) * D_ + h * DK_;
    const float* vb = Vg + ((size_t)b * T_) * D_ + h * DK_;
    const float* biasb = g_bias + b * T_;

    for (int s0 = 0; s0 < T_; s0 += 16) {
        __syncthreads();
        {
            int idx = threadIdx.x;                  // 0..127
            int r = idx >> 4, c = idx & 15;
            Ks[idx] = *(const float4*)(kb + (size_t)(s0 + r) * D_ + 4 * c);
            Vs[idx] = *(const float4*)(vb + (size_t)(s0 + r) * D_ + 4 * c);
            int idx2 = idx + 128;
            int r2 = idx2 >> 4, c2 = idx2 & 15;
            Ks[idx2] = *(const float4*)(kb + (size_t)(s0 + r2) * D_ + 4 * c2);
            Vs[idx2] = *(const float4*)(vb + (size_t)(s0 + r2) * D_ + 4 * c2);
            if (idx < 16) Bs[idx] = biasb[s0 + idx];
        }
        __syncthreads();

        float sv[16];
#pragma unroll
        for (int j = 0; j < 16; j++) {
            float p0 = 0.f, p1 = 0.f, p2 = 0.f, p3 = 0.f;
#pragma unroll
            for (int c = 0; c < 16; c++) {
                float4 kv = Ks[j * 16 + c];
                float4 qq = q[c];
                p0 += qq.x * kv.x; p1 += qq.y * kv.y;
                p2 += qq.z * kv.z; p3 += qq.w * kv.w;
            }
            sv[j] = ((p0 + p1) + (p2 + p3)) * SCALE_ + Bs[j];
        }

        float nm = mx;
#pragma unroll
        for (int j = 0; j < 16; j++) nm = fmaxf(nm, sv[j]);
        float corr = __expf(mx - nm);
        mx = nm;
        l *= corr;
#pragma unroll
        for (int c = 0; c < 16; c++) {
            o[c].x *= corr; o[c].y *= corr; o[c].z *= corr; o[c].w *= corr;
        }
#pragma unroll
        for (int j = 0; j < 16; j++) {
            float p = __expf(sv[j] - nm);
            l += p;
#pragma unroll
            for (int c = 0; c < 16; c++) {
                float4 vv = Vs[j * 16 + c];
                o[c].x += p * vv.x; o[c].y += p * vv.y;
                o[c].z += p * vv.z; o[c].w += p * vv.w;
            }
        }
    }

    float inv = 1.f / l;
    float* op = CTX + qoff;
#pragma unroll
    for (int c = 0; c < 16; c++) {
        float4 ov = make_float4(o[c].x * inv, o[c].y * inv,
                                o[c].z * inv, o[c].w * inv);
        *(float4*)(op + 4 * c) = ov;
    }
}

// ---------------- launch ----------------
extern "C" void kernel_launch(void* const* d_in, const int* in_sizes, int n_in,
                              void* d_out, int out_size)
{
    const float* query = (const float*)d_in[0];
    const float* key   = (const float*)d_in[1];
    const float* value = (const float*)d_in[2];
    const void*  mask  = d_in[3];
    const float* Wq = (const float*)d_in[4];  const float* bq = (const float*)d_in[5];
    const float* Wk = (const float*)d_in[6];  const float* bk = (const float*)d_in[7];
    const float* Wv = (const float*)d_in[8];  const float* bv = (const float*)d_in[9];
    const float* Wo = (const float*)d_in[10]; const float* bo = (const float*)d_in[11];

    float *Qb, *Kb, *Vb, *Cb;
    cudaGetSymbolAddress((void**)&Qb, g_Q);
    cudaGetSymbolAddress((void**)&Kb, g_K);
    cudaGetSymbolAddress((void**)&Vb, g_V);
    cudaGetSymbolAddress((void**)&Cb, g_CTX);

    detect_mask_kernel<<<1, 256>>>((const unsigned int*)mask);
    build_bias_kernel<<<(M_ + 255) / 256, 256>>>(mask);

    dim3 gg(D_ / 128, M_ / 64);   // (8, 64)
    gemm_tf32x3_kernel<<<gg, 256>>>(query, Wq, bq, Qb);
    gemm_tf32x3_kernel<<<gg, 256>>>(key,   Wk, bk, Kb);
    gemm_tf32x3_kernel<<<gg, 256>>>(value, Wv, bv, Vb);

    attn_kernel<<<dim3(T_ / 128, H_, B_), 128>>>(Qb, Kb, Vb, Cb);

    gemm_tf32x3_kernel<<<gg, 256>>>(Cb, Wo, bo, (float*)d_out);
}

// round 3
// speedup vs baseline: 1.9166x; 1.6408x over previous
#include <cuda_runtime.h>
#include <cstdint>

#define B_ 2
#define T_ 2048
#define D_ 1024
#define H_ 16
#define DK_ 64
#define M_ (B_*T_)           // 4096 rows
#define SCALE_ 0.125f        // 1/sqrt(64)

// ---------------- scratch (device globals; no allocations allowed) ----------
__device__ float g_Q[M_*D_];
__device__ float g_K[M_*D_];
__device__ float g_V[M_*D_];
__device__ float g_CTX[M_*D_];
__device__ float g_bias[M_];
__device__ int   g_maskmode;   // 0=int32, 1=float32, 2=uint8

// ---------------- mask dtype detection ----------------
__global__ void detect_mask_kernel(const unsigned int* __restrict__ w) {
    __shared__ int s_badint, s_badfloat;
    if (threadIdx.x == 0) { s_badint = 0; s_badfloat = 0; }
    __syncthreads();
    int bi = 0, bf = 0;
    for (int i = threadIdx.x; i < 1024; i += blockDim.x) {
        unsigned v = w[i];
        if (v > 1u) bi = 1;
        if (v != 0u && v != 0x3F800000u) bf = 1;
    }
    if (bi) atomicOr(&s_badint, 1);
    if (bf) atomicOr(&s_badfloat, 1);
    __syncthreads();
    if (threadIdx.x == 0)
        g_maskmode = (!s_badint) ? 0 : ((!s_badfloat) ? 1 : 2);
}

__global__ void build_bias_kernel(const void* __restrict__ mask) {
    int i = blockIdx.x * blockDim.x + threadIdx.x;
    if (i >= M_) return;
    int mode = g_maskmode;
    bool keep;
    if (mode == 0)      keep = ((const int*)mask)[i] != 0;
    else if (mode == 1) keep = ((const float*)mask)[i] != 0.0f;
    else                keep = ((const unsigned char*)mask)[i] != 0;
    g_bias[i] = keep ? 0.0f : -1e30f;
}

// ---------------- tf32 helpers ----------------
__device__ __forceinline__ void mma_tf32(float* d, const uint32_t* a, const uint32_t* b) {
    asm volatile(
        "mma.sync.aligned.m16n8k8.row.col.f32.tf32.tf32.f32 "
        "{%0,%1,%2,%3}, {%4,%5,%6,%7}, {%8,%9}, {%0,%1,%2,%3};"
        : "+f"(d[0]), "+f"(d[1]), "+f"(d[2]), "+f"(d[3])
        : "r"(a[0]), "r"(a[1]), "r"(a[2]), "r"(a[3]), "r"(b[0]), "r"(b[1]));
}

__device__ __forceinline__ void split_tf32(float x, uint32_t& hi, uint32_t& lo) {
    uint32_t h = __float_as_uint(x) & 0xFFFFE000u;
    hi = h;
    lo = __float_as_uint(x - __uint_as_float(h));
}

__device__ __forceinline__ uint32_t f2tf32(float x) {
    uint32_t r;
    asm("cvt.rna.tf32.f32 %0, %1;" : "=r"(r) : "f"(x));
    return r;
}

// ================= tf32x3 tensor-core GEMM (validated R2) ==================
#define TSTRIDE 20

__global__ __launch_bounds__(256) void gemm_tf32x3_kernel(
    const float* __restrict__ A, const float* __restrict__ W,
    const float* __restrict__ bvec, float* __restrict__ C)
{
    __shared__ float As[2][64 * TSTRIDE];
    __shared__ float Bs[2][128 * TSTRIDE];

    const int tid  = threadIdx.x;
    const int lane = tid & 31;
    const int wid  = tid >> 5;
    const int wm   = (wid >> 2) * 32;
    const int wn   = (wid & 3) * 32;
    const int gid  = lane >> 2;
    const int tig  = lane & 3;

    const int m0 = blockIdx.y * 64;
    const int n0 = blockIdx.x * 128;

    float acc[2][4][4];
#pragma unroll
    for (int mt = 0; mt < 2; mt++)
#pragma unroll
        for (int nt = 0; nt < 4; nt++)
#pragma unroll
            for (int i = 0; i < 4; i++) acc[mt][nt][i] = 0.f;

    const int arow = tid >> 2;
    const int acg  = (tid & 3) * 4;
    const float* Ag  = A + (size_t)(m0 + arow) * 1024 + acg;
    const float* Wg0 = W + (size_t)(n0 + arow) * 1024 + acg;
    const float* Wg1 = W + (size_t)(n0 + arow + 64) * 1024 + acg;

    float4 pa, pb0, pb1;
    pa  = *(const float4*)(Ag);
    pb0 = *(const float4*)(Wg0);
    pb1 = *(const float4*)(Wg1);

#define GEMM_STORE(BUF)                                                     \
    do {                                                                    \
        *(float4*)&As[BUF][arow * TSTRIDE + acg]        = pa;               \
        *(float4*)&Bs[BUF][arow * TSTRIDE + acg]        = pb0;              \
        *(float4*)&Bs[BUF][(arow + 64) * TSTRIDE + acg] = pb1;              \
    } while (0)

#define GEMM_COMPUTE(BUF)                                                   \
    do {                                                                    \
        _Pragma("unroll")                                                   \
        for (int kc = 0; kc < 2; kc++) {                                    \
            const int kb = kc * 8;                                          \
            uint32_t Ah[2][4], Al[2][4], Bh[4][2], Bl[4][2];                \
            _Pragma("unroll")                                               \
            for (int mt = 0; mt < 2; mt++) {                                \
                const float* ap = &As[BUF][(wm + mt * 16 + gid) * TSTRIDE + kb + tig]; \
                float x0 = ap[0];                                           \
                float x1 = ap[8 * TSTRIDE];                                 \
                float x2 = ap[4];                                           \
                float x3 = ap[8 * TSTRIDE + 4];                             \
                split_tf32(x0, Ah[mt][0], Al[mt][0]);                       \
                split_tf32(x1, Ah[mt][1], Al[mt][1]);                       \
                split_tf32(x2, Ah[mt][2], Al[mt][2]);                       \
                split_tf32(x3, Ah[mt][3], Al[mt][3]);                       \
            }                                                               \
            _Pragma("unroll")                                               \
            for (int nt = 0; nt < 4; nt++) {                                \
                const float* bp = &Bs[BUF][(wn + nt * 8 + gid) * TSTRIDE + kb + tig]; \
                float y0 = bp[0];                                           \
                float y1 = bp[4];                                           \
                split_tf32(y0, Bh[nt][0], Bl[nt][0]);                       \
                split_tf32(y1, Bh[nt][1], Bl[nt][1]);                       \
            }                                                               \
            _Pragma("unroll")                                               \
            for (int mt = 0; mt < 2; mt++)                                  \
                _Pragma("unroll")                                           \
                for (int nt = 0; nt < 4; nt++) {                            \
                    mma_tf32(acc[mt][nt], Ah[mt], Bh[nt]);                  \
                    mma_tf32(acc[mt][nt], Al[mt], Bh[nt]);                  \
                    mma_tf32(acc[mt][nt], Ah[mt], Bl[nt]);                  \
                }                                                           \
        }                                                                   \
    } while (0)

    GEMM_STORE(0);
    __syncthreads();

    int buf = 0;
    for (int k0 = 16; k0 < 1024; k0 += 16) {
        pa  = *(const float4*)(Ag + k0);
        pb0 = *(const float4*)(Wg0 + k0);
        pb1 = *(const float4*)(Wg1 + k0);
        if (buf == 0) GEMM_COMPUTE(0); else GEMM_COMPUTE(1);
        __syncthreads();
        if (buf == 0) GEMM_STORE(1); else GEMM_STORE(0);
        __syncthreads();
        buf ^= 1;
    }
    if (buf == 0) GEMM_COMPUTE(0); else GEMM_COMPUTE(1);

#pragma unroll
    for (int mt = 0; mt < 2; mt++) {
#pragma unroll
        for (int nt = 0; nt < 4; nt++) {
            int gm = m0 + wm + mt * 16 + gid;
            int gn = n0 + wn + nt * 8 + tig * 2;
            float b0 = __ldg(bvec + gn);
            float b1 = __ldg(bvec + gn + 1);
            *(float2*)&C[(size_t)gm * 1024 + gn] =
                make_float2(acc[mt][nt][0] + b0, acc[mt][nt][1] + b1);
            *(float2*)&C[(size_t)(gm + 8) * 1024 + gn] =
                make_float2(acc[mt][nt][2] + b0, acc[mt][nt][3] + b1);
        }
    }
}

// ================= tensor-core flash attention ==================
// 8 warps, 128 q-rows/block (16/warp). S-tiles of 32 keys.
// QK^T: tf32 x1 (cvt.rna operands). P*V: tf32 x3 (P and V hi/lo split).
#define KPAD 68
#define VPAD 72
#define PPAD 36

__global__ __launch_bounds__(256) void attn_mma_kernel(
    const float* __restrict__ Qg, const float* __restrict__ Kg,
    const float* __restrict__ Vg, float* __restrict__ CTX)
{
    __shared__ float Ks[32 * KPAD];
    __shared__ float Vhs[32 * VPAD];
    __shared__ float Vls[32 * VPAD];
    __shared__ float Pb[8][16 * PPAD];
    __shared__ float Bs[32];

    const int tid  = threadIdx.x;
    const int lane = tid & 31, wid = tid >> 5;
    const int gid  = lane >> 2, tig = lane & 3;
    const int b = blockIdx.z, h = blockIdx.y;
    const int t0 = blockIdx.x * 128;

    const size_t kvBase = ((size_t)b * T_) * D_ + h * DK_;

    // ---- Q fragments: tf32-rounded, registers, reused for all S-tiles ----
    uint32_t Qr[8][4];
    {
        const int r0 = t0 + wid * 16 + gid;
        const float* q0 = Qg + ((size_t)(b * T_) + r0) * D_ + h * DK_;
        const float* q1 = q0 + 8 * D_;
#pragma unroll
        for (int ks = 0; ks < 8; ks++) {
            int c = ks * 8 + tig;
            Qr[ks][0] = f2tf32(q0[c]);
            Qr[ks][1] = f2tf32(q1[c]);
            Qr[ks][2] = f2tf32(q0[c + 4]);
            Qr[ks][3] = f2tf32(q1[c + 4]);
        }
    }

    float oacc[8][4];
#pragma unroll
    for (int nt = 0; nt < 8; nt++)
#pragma unroll
        for (int i = 0; i < 4; i++) oacc[nt][i] = 0.f;
    float m0 = -1e30f, m1 = -1e30f, l0 = 0.f, l1 = 0.f;

    // ---- fill mapping + prefetch ----
    const int frow = tid >> 4;           // 0..15
    const int fc4  = (tid & 15) * 4;     // 0..60
    const float* kRow = Kg + kvBase + (size_t)frow * D_ + fc4;
    const float* vRow = Vg + kvBase + (size_t)frow * D_ + fc4;

    float4 ka  = *(const float4*)(kRow);
    float4 kb4 = *(const float4*)(kRow + 16 * D_);
    float4 va  = *(const float4*)(vRow);
    float4 vb4 = *(const float4*)(vRow + 16 * D_);

    for (int s0 = 0; s0 < T_; s0 += 32) {
        __syncthreads();
        // store prefetched tile (K: tf32-rounded; V: hi/lo split)
        {
            float* kd0 = &Ks[frow * KPAD + fc4];
            kd0[0] = __uint_as_float(f2tf32(ka.x));
            kd0[1] = __uint_as_float(f2tf32(ka.y));
            kd0[2] = __uint_as_float(f2tf32(ka.z));
            kd0[3] = __uint_as_float(f2tf32(ka.w));
            float* kd1 = &Ks[(frow + 16) * KPAD + fc4];
            kd1[0] = __uint_as_float(f2tf32(kb4.x));
            kd1[1] = __uint_as_float(f2tf32(kb4.y));
            kd1[2] = __uint_as_float(f2tf32(kb4.z));
            kd1[3] = __uint_as_float(f2tf32(kb4.w));

            uint32_t hi, lo;
            float* vh0 = &Vhs[frow * VPAD + fc4];
            float* vl0 = &Vls[frow * VPAD + fc4];
            split_tf32(va.x, hi, lo); vh0[0] = __uint_as_float(hi); vl0[0] = __uint_as_float(lo);
            split_tf32(va.y, hi, lo); vh0[1] = __uint_as_float(hi); vl0[1] = __uint_as_float(lo);
            split_tf32(va.z, hi, lo); vh0[2] = __uint_as_float(hi); vl0[2] = __uint_as_float(lo);
            split_tf32(va.w, hi, lo); vh0[3] = __uint_as_float(hi); vl0[3] = __uint_as_float(lo);
            float* vh1 = &Vhs[(frow + 16) * VPAD + fc4];
            float* vl1 = &Vls[(frow + 16) * VPAD + fc4];
            split_tf32(vb4.x, hi, lo); vh1[0] = __uint_as_float(hi); vl1[0] = __uint_as_float(lo);
            split_tf32(vb4.y, hi, lo); vh1[1] = __uint_as_float(hi); vl1[1] = __uint_as_float(lo);
            split_tf32(vb4.z, hi, lo); vh1[2] = __uint_as_float(hi); vl1[2] = __uint_as_float(lo);
            split_tf32(vb4.w, hi, lo); vh1[3] = __uint_as_float(hi); vl1[3] = __uint_as_float(lo);

            if (tid < 32) Bs[tid] = g_bias[b * T_ + s0 + tid];
        }
        __syncthreads();

        // prefetch next tile
        if (s0 + 32 < T_) {
            ka  = *(const float4*)(kRow + (size_t)(s0 + 32) * D_);
            kb4 = *(const float4*)(kRow + (size_t)(s0 + 48) * D_);
            va  = *(const float4*)(vRow + (size_t)(s0 + 32) * D_);
            vb4 = *(const float4*)(vRow + (size_t)(s0 + 48) * D_);
        }

        // ---- S = Q K^T (tf32 x1) ----
        float sacc[4][4];
#pragma unroll
        for (int nt = 0; nt < 4; nt++)
#pragma unroll
            for (int i = 0; i < 4; i++) sacc[nt][i] = 0.f;
#pragma unroll
        for (int ks = 0; ks < 8; ks++) {
            const int kb = ks * 8;
#pragma unroll
            for (int nt = 0; nt < 4; nt++) {
                const float* kp = &Ks[(nt * 8 + gid) * KPAD + kb + tig];
                uint32_t bf[2];
                bf[0] = __float_as_uint(kp[0]);
                bf[1] = __float_as_uint(kp[4]);
                mma_tf32(sacc[nt], Qr[ks], bf);
            }
        }

        // ---- scale + bias, online softmax ----
        float sv[4][4];
#pragma unroll
        for (int nt = 0; nt < 4; nt++) {
            int c0 = nt * 8 + 2 * tig;
            float bb0 = Bs[c0], bb1 = Bs[c0 + 1];
            sv[nt][0] = sacc[nt][0] * SCALE_ + bb0;
            sv[nt][1] = sacc[nt][1] * SCALE_ + bb1;
            sv[nt][2] = sacc[nt][2] * SCALE_ + bb0;
            sv[nt][3] = sacc[nt][3] * SCALE_ + bb1;
        }
        float mx0 = fmaxf(fmaxf(sv[0][0], sv[0][1]), fmaxf(sv[1][0], sv[1][1]));
        mx0 = fmaxf(mx0, fmaxf(fmaxf(sv[2][0], sv[2][1]), fmaxf(sv[3][0], sv[3][1])));
        float mx1 = fmaxf(fmaxf(sv[0][2], sv[0][3]), fmaxf(sv[1][2], sv[1][3]));
        mx1 = fmaxf(mx1, fmaxf(fmaxf(sv[2][2], sv[2][3]), fmaxf(sv[3][2], sv[3][3])));
        mx0 = fmaxf(mx0, __shfl_xor_sync(0xffffffffu, mx0, 1));
        mx0 = fmaxf(mx0, __shfl_xor_sync(0xffffffffu, mx0, 2));
        mx1 = fmaxf(mx1, __shfl_xor_sync(0xffffffffu, mx1, 1));
        mx1 = fmaxf(mx1, __shfl_xor_sync(0xffffffffu, mx1, 2));

        float m0n = fmaxf(m0, mx0), m1n = fmaxf(m1, mx1);
        float c0f = __expf(m0 - m0n), c1f = __expf(m1 - m1n);
        m0 = m0n; m1 = m1n;

        float rs0 = 0.f, rs1 = 0.f;
#pragma unroll
        for (int nt = 0; nt < 4; nt++) {
            float p0 = __expf(sv[nt][0] - m0n);
            float p1 = __expf(sv[nt][1] - m0n);
            float p2 = __expf(sv[nt][2] - m1n);
            float p3 = __expf(sv[nt][3] - m1n);
            rs0 += p0 + p1; rs1 += p2 + p3;
            int c0 = nt * 8 + 2 * tig;
            Pb[wid][gid * PPAD + c0]           = p0;
            Pb[wid][gid * PPAD + c0 + 1]       = p1;
            Pb[wid][(gid + 8) * PPAD + c0]     = p2;
            Pb[wid][(gid + 8) * PPAD + c0 + 1] = p3;
        }
        rs0 += __shfl_xor_sync(0xffffffffu, rs0, 1);
        rs0 += __shfl_xor_sync(0xffffffffu, rs0, 2);
        rs1 += __shfl_xor_sync(0xffffffffu, rs1, 1);
        rs1 += __shfl_xor_sync(0xffffffffu, rs1, 2);
        l0 = l0 * c0f + rs0;
        l1 = l1 * c1f + rs1;
#pragma unroll
        for (int nt = 0; nt < 8; nt++) {
            oacc[nt][0] *= c0f; oacc[nt][1] *= c0f;
            oacc[nt][2] *= c1f; oacc[nt][3] *= c1f;
        }
        __syncwarp();

        // ---- O += P V (tf32 x3) ----
#pragma unroll
        for (int kk = 0; kk < 4; kk++) {
            const float* pr = &Pb[wid][gid * PPAD + kk * 8 + tig];
            uint32_t ah[4], al[4];
            split_tf32(pr[0],            ah[0], al[0]);
            split_tf32(pr[8 * PPAD],     ah[1], al[1]);
            split_tf32(pr[4],            ah[2], al[2]);
            split_tf32(pr[8 * PPAD + 4], ah[3], al[3]);
#pragma unroll
            for (int nt = 0; nt < 8; nt++) {
                const float* vh = &Vhs[(kk * 8 + tig) * VPAD + nt * 8 + gid];
                const float* vl = &Vls[(kk * 8 + tig) * VPAD + nt * 8 + gid];
                uint32_t bh[2], bl[2];
                bh[0] = __float_as_uint(vh[0]);
                bh[1] = __float_as_uint(vh[4 * VPAD]);
                bl[0] = __float_as_uint(vl[0]);
                bl[1] = __float_as_uint(vl[4 * VPAD]);
                mma_tf32(oacc[nt], ah, bh);
                mma_tf32(oacc[nt], al, bh);
                mma_tf32(oacc[nt], ah, bl);
            }
        }
        __syncwarp();
    }

    // ---- epilogue ----
    float inv0 = 1.f / l0, inv1 = 1.f / l1;
    const int gr0 = t0 + wid * 16 + gid;
    float* o0 = CTX + ((size_t)(b * T_) + gr0) * D_ + h * DK_;
    float* o1 = o0 + 8 * D_;
#pragma unroll
    for (int nt = 0; nt < 8; nt++) {
        int c = nt * 8 + 2 * tig;
        *(float2*)(o0 + c) = make_float2(oacc[nt][0] * inv0, oacc[nt][1] * inv0);
        *(float2*)(o1 + c) = make_float2(oacc[nt][2] * inv1, oacc[nt][3] * inv1);
    }
}

// ---------------- launch ----------------
extern "C" void kernel_launch(void* const* d_in, const int* in_sizes, int n_in,
                              void* d_out, int out_size)
{
    const float* query = (const float*)d_in[0];
    const float* key   = (const float*)d_in[1];
    const float* value = (const float*)d_in[2];
    const void*  mask  = d_in[3];
    const float* Wq = (const float*)d_in[4];  const float* bq = (const float*)d_in[5];
    const float* Wk = (const float*)d_in[6];  const float* bk = (const float*)d_in[7];
    const float* Wv = (const float*)d_in[8];  const float* bv = (const float*)d_in[9];
    const float* Wo = (const float*)d_in[10]; const float* bo = (const float*)d_in[11];

    float *Qb, *Kb, *Vb, *Cb;
    cudaGetSymbolAddress((void**)&Qb, g_Q);
    cudaGetSymbolAddress((void**)&Kb, g_K);
    cudaGetSymbolAddress((void**)&Vb, g_V);
    cudaGetSymbolAddress((void**)&Cb, g_CTX);

    detect_mask_kernel<<<1, 256>>>((const unsigned int*)mask);
    build_bias_kernel<<<(M_ + 255) / 256, 256>>>(mask);

    dim3 gg(D_ / 128, M_ / 64);   // (8, 64)
    gemm_tf32x3_kernel<<<gg, 256>>>(query, Wq, bq, Qb);
    gemm_tf32x3_kernel<<<gg, 256>>>(key,   Wk, bk, Kb);
    gemm_tf32x3_kernel<<<gg, 256>>>(value, Wv, bv, Vb);

    attn_mma_kernel<<<dim3(T_ / 128, H_, B_), 256>>>(Qb, Kb, Vb, Cb);

    gemm_tf32x3_kernel<<<gg, 256>>>(Cb, Wo, bo, (float*)d_out);
}

// round 4
// speedup vs baseline: 2.6551x; 1.3853x over previous
#include <cuda_runtime.h>
#include <cuda_bf16.h>
#include <cstdint>

#define B_ 2
#define T_ 2048
#define D_ 1024
#define H_ 16
#define DK_ 64
#define M_ (B_*T_)           // 4096 rows
#define SCALE_ 0.125f        // 1/sqrt(64)

// ---------------- scratch (device globals; no allocations allowed) ----------
__device__ float g_Q[M_*D_];
__device__ float g_K[M_*D_];
__device__ float g_V[M_*D_];
__device__ float g_CTX[M_*D_];
__device__ float g_bias[M_];
__device__ int   g_maskmode;   // 0=int32, 1=float32, 2=uint8

// ---------------- mask dtype detection ----------------
__global__ void detect_mask_kernel(const unsigned int* __restrict__ w) {
    __shared__ int s_badint, s_badfloat;
    if (threadIdx.x == 0) { s_badint = 0; s_badfloat = 0; }
    __syncthreads();
    int bi = 0, bf = 0;
    for (int i = threadIdx.x; i < 1024; i += blockDim.x) {
        unsigned v = w[i];
        if (v > 1u) bi = 1;
        if (v != 0u && v != 0x3F800000u) bf = 1;
    }
    if (bi) atomicOr(&s_badint, 1);
    if (bf) atomicOr(&s_badfloat, 1);
    __syncthreads();
    if (threadIdx.x == 0)
        g_maskmode = (!s_badint) ? 0 : ((!s_badfloat) ? 1 : 2);
}

__global__ void build_bias_kernel(const void* __restrict__ mask) {
    int i = blockIdx.x * blockDim.x + threadIdx.x;
    if (i >= M_) return;
    int mode = g_maskmode;
    bool keep;
    if (mode == 0)      keep = ((const int*)mask)[i] != 0;
    else if (mode == 1) keep = ((const float*)mask)[i] != 0.0f;
    else                keep = ((const unsigned char*)mask)[i] != 0;
    g_bias[i] = keep ? 0.0f : -1e30f;
}

// ---------------- mma helpers ----------------
__device__ __forceinline__ void mma_tf32(float* d, const uint32_t* a, const uint32_t* b) {
    asm volatile(
        "mma.sync.aligned.m16n8k8.row.col.f32.tf32.tf32.f32 "
        "{%0,%1,%2,%3}, {%4,%5,%6,%7}, {%8,%9}, {%0,%1,%2,%3};"
        : "+f"(d[0]), "+f"(d[1]), "+f"(d[2]), "+f"(d[3])
        : "r"(a[0]), "r"(a[1]), "r"(a[2]), "r"(a[3]), "r"(b[0]), "r"(b[1]));
}

__device__ __forceinline__ void mma_bf16(float* d, const uint32_t* a, const uint32_t* b) {
    asm volatile(
        "mma.sync.aligned.m16n8k16.row.col.f32.bf16.bf16.f32 "
        "{%0,%1,%2,%3}, {%4,%5,%6,%7}, {%8,%9}, {%0,%1,%2,%3};"
        : "+f"(d[0]), "+f"(d[1]), "+f"(d[2]), "+f"(d[3])
        : "r"(a[0]), "r"(a[1]), "r"(a[2]), "r"(a[3]), "r"(b[0]), "r"(b[1]));
}

__device__ __forceinline__ uint32_t f2tf32(float x) {
    uint32_t r;
    asm("cvt.rna.tf32.f32 %0, %1;" : "=r"(r) : "f"(x));
    return r;
}

__device__ __forceinline__ void split_bf(float x, float& h, float& l) {
    h = __bfloat162float(__float2bfloat16(x));
    l = x - h;
}

__device__ __forceinline__ uint32_t packbf(float a, float b) {
    __nv_bfloat162 t = __floats2bfloat162_rn(a, b);   // low half = a (even k)
    return *reinterpret_cast<uint32_t*>(&t);
}

// ================= bf16x3 tensor-core GEMM ==================
// C[M,N] = A[M,K] @ W[N,K]^T + b[N]. Block 64x128, 8 warps (2m x 4n),
// k-step 16, m16n8k16 bf16, hi/lo planes pre-split+packed at smem fill.
#define ASTR 12   // uint32 stride per row (8 pairs used); conflict-free

__global__ __launch_bounds__(256) void gemm_bf16x3_kernel(
    const float* __restrict__ A, const float* __restrict__ W,
    const float* __restrict__ bvec, float* __restrict__ C)
{
    __shared__ uint32_t Ahs[2][64 * ASTR];
    __shared__ uint32_t Als[2][64 * ASTR];
    __shared__ uint32_t Bhs[2][128 * ASTR];
    __shared__ uint32_t Bls[2][128 * ASTR];

    const int tid  = threadIdx.x;
    const int lane = tid & 31, wid = tid >> 5;
    const int wm   = (wid >> 2) * 32;
    const int wn   = (wid & 3) * 32;
    const int gid  = lane >> 2, tig = lane & 3;
    const int m0 = blockIdx.y * 64;
    const int n0 = blockIdx.x * 128;

    float acc[2][4][4];
#pragma unroll
    for (int mt = 0; mt < 2; mt++)
#pragma unroll
        for (int nt = 0; nt < 4; nt++)
#pragma unroll
            for (int i = 0; i < 4; i++) acc[mt][nt][i] = 0.f;

    const int arow = tid >> 2;
    const int acg  = (tid & 3) * 4;
    const int pb2  = (tid & 3) * 2;
    const float* Ag  = A + (size_t)(m0 + arow) * 1024 + acg;
    const float* Wg0 = W + (size_t)(n0 + arow) * 1024 + acg;
    const float* Wg1 = W + (size_t)(n0 + arow + 64) * 1024 + acg;

    float4 pa, pw0, pw1;
    pa  = *(const float4*)(Ag);
    pw0 = *(const float4*)(Wg0);
    pw1 = *(const float4*)(Wg1);

#define GSTORE(BUF)                                                           \
    do {                                                                      \
        float h0,h1,h2,h3,l0,l1,l2,l3;                                        \
        split_bf(pa.x,h0,l0); split_bf(pa.y,h1,l1);                           \
        split_bf(pa.z,h2,l2); split_bf(pa.w,h3,l3);                           \
        *(uint2*)&Ahs[BUF][arow*ASTR+pb2] = make_uint2(packbf(h0,h1),packbf(h2,h3)); \
        *(uint2*)&Als[BUF][arow*ASTR+pb2] = make_uint2(packbf(l0,l1),packbf(l2,l3)); \
        split_bf(pw0.x,h0,l0); split_bf(pw0.y,h1,l1);                         \
        split_bf(pw0.z,h2,l2); split_bf(pw0.w,h3,l3);                         \
        *(uint2*)&Bhs[BUF][arow*ASTR+pb2] = make_uint2(packbf(h0,h1),packbf(h2,h3)); \
        *(uint2*)&Bls[BUF][arow*ASTR+pb2] = make_uint2(packbf(l0,l1),packbf(l2,l3)); \
        split_bf(pw1.x,h0,l0); split_bf(pw1.y,h1,l1);                         \
        split_bf(pw1.z,h2,l2); split_bf(pw1.w,h3,l3);                         \
        *(uint2*)&Bhs[BUF][(arow+64)*ASTR+pb2] = make_uint2(packbf(h0,h1),packbf(h2,h3)); \
        *(uint2*)&Bls[BUF][(arow+64)*ASTR+pb2] = make_uint2(packbf(l0,l1),packbf(l2,l3)); \
    } while (0)

#define GCOMP(BUF)                                                            \
    do {                                                                      \
        uint32_t a_h[2][4], a_l[2][4], b_h[4][2], b_l[4][2];                  \
        _Pragma("unroll")                                                     \
        for (int mt = 0; mt < 2; mt++) {                                      \
            int r  = (wm + mt*16 + gid) * ASTR;                               \
            int r8 = (wm + mt*16 + gid + 8) * ASTR;                           \
            a_h[mt][0] = Ahs[BUF][r  + tig];                                  \
            a_h[mt][1] = Ahs[BUF][r8 + tig];                                  \
            a_h[mt][2] = Ahs[BUF][r  + tig + 4];                              \
            a_h[mt][3] = Ahs[BUF][r8 + tig + 4];                              \
            a_l[mt][0] = Als[BUF][r  + tig];                                  \
            a_l[mt][1] = Als[BUF][r8 + tig];                                  \
            a_l[mt][2] = Als[BUF][r  + tig + 4];                              \
            a_l[mt][3] = Als[BUF][r8 + tig + 4];                              \
        }                                                                     \
        _Pragma("unroll")                                                     \
        for (int nt = 0; nt < 4; nt++) {                                      \
            int n = (wn + nt*8 + gid) * ASTR;                                 \
            b_h[nt][0] = Bhs[BUF][n + tig];                                   \
            b_h[nt][1] = Bhs[BUF][n + tig + 4];                               \
            b_l[nt][0] = Bls[BUF][n + tig];                                   \
            b_l[nt][1] = Bls[BUF][n + tig + 4];                               \
        }                                                                     \
        _Pragma("unroll")                                                     \
        for (int mt = 0; mt < 2; mt++)                                        \
            _Pragma("unroll")                                                 \
            for (int nt = 0; nt < 4; nt++) {                                  \
                mma_bf16(acc[mt][nt], a_h[mt], b_h[nt]);                      \
                mma_bf16(acc[mt][nt], a_l[mt], b_h[nt]);                      \
                mma_bf16(acc[mt][nt], a_h[mt], b_l[nt]);                      \
            }                                                                 \
    } while (0)

    GSTORE(0);
    __syncthreads();

    int buf = 0;
    for (int k0 = 16; k0 < 1024; k0 += 16) {
        pa  = *(const float4*)(Ag + k0);
        pw0 = *(const float4*)(Wg0 + k0);
        pw1 = *(const float4*)(Wg1 + k0);
        if (buf == 0) GCOMP(0); else GCOMP(1);
        __syncthreads();
        if (buf == 0) GSTORE(1); else GSTORE(0);
        __syncthreads();
        buf ^= 1;
    }
    if (buf == 0) GCOMP(0); else GCOMP(1);

#pragma unroll
    for (int mt = 0; mt < 2; mt++) {
#pragma unroll
        for (int nt = 0; nt < 4; nt++) {
            int gm = m0 + wm + mt * 16 + gid;
            int gn = n0 + wn + nt * 8 + tig * 2;
            float b0 = __ldg(bvec + gn);
            float b1 = __ldg(bvec + gn + 1);
            *(float2*)&C[(size_t)gm * 1024 + gn] =
                make_float2(acc[mt][nt][0] + b0, acc[mt][nt][1] + b1);
            *(float2*)&C[(size_t)(gm + 8) * 1024 + gn] =
                make_float2(acc[mt][nt][2] + b0, acc[mt][nt][3] + b1);
        }
    }
}

// ================= tensor-core flash attention ==================
// QK^T: tf32 x1. P*V: bf16 x3 (m16n8k16), V and P pre-split into packed
// bf16x2 hi/lo planes.
#define KPAD 68
#define VSTR 72   // uint32 stride per k-pair row of V planes
#define PSTR 20   // uint32 stride per row of P planes

__global__ __launch_bounds__(256) void attn_mma_kernel(
    const float* __restrict__ Qg, const float* __restrict__ Kg,
    const float* __restrict__ Vg, float* __restrict__ CTX)
{
    __shared__ float    Ks[32 * KPAD];
    __shared__ uint32_t Vh[16 * VSTR];
    __shared__ uint32_t Vl[16 * VSTR];
    __shared__ uint32_t Ph[8][16 * PSTR];
    __shared__ uint32_t Pl[8][16 * PSTR];
    __shared__ float    Bs[32];

    const int tid  = threadIdx.x;
    const int lane = tid & 31, wid = tid >> 5;
    const int gid  = lane >> 2, tig = lane & 3;
    const int b = blockIdx.z, h = blockIdx.y;
    const int t0 = blockIdx.x * 128;

    const size_t kvBase = ((size_t)b * T_) * D_ + h * DK_;

    // ---- Q fragments: tf32-rounded, registers ----
    uint32_t Qr[8][4];
    {
        const int r0 = t0 + wid * 16 + gid;
        const float* q0 = Qg + ((size_t)(b * T_) + r0) * D_ + h * DK_;
        const float* q1 = q0 + 8 * D_;
#pragma unroll
        for (int ks = 0; ks < 8; ks++) {
            int c = ks * 8 + tig;
            Qr[ks][0] = f2tf32(q0[c]);
            Qr[ks][1] = f2tf32(q1[c]);
            Qr[ks][2] = f2tf32(q0[c + 4]);
            Qr[ks][3] = f2tf32(q1[c + 4]);
        }
    }

    float oacc[8][4];
#pragma unroll
    for (int nt = 0; nt < 8; nt++)
#pragma unroll
        for (int i = 0; i < 4; i++) oacc[nt][i] = 0.f;
    float m0 = -1e30f, m1 = -1e30f, l0 = 0.f, l1 = 0.f;

    // ---- fill mappings + prefetch ----
    const int frow = tid >> 4;           // K: 0..15
    const int fc4  = (tid & 15) * 4;
    const float* kRow = Kg + kvBase + (size_t)frow * D_ + fc4;

    const int vp  = tid >> 4;            // V: k-pair 0..15
    const int vcg = (tid & 15) * 4;
    const float* vRow0 = Vg + kvBase + (size_t)(2 * vp) * D_ + vcg;
    const float* vRow1 = vRow0 + D_;

    float4 ka  = *(const float4*)(kRow);
    float4 kb4 = *(const float4*)(kRow + 16 * D_);
    float4 va0 = *(const float4*)(vRow0);
    float4 va1 = *(const float4*)(vRow1);

    for (int s0 = 0; s0 < T_; s0 += 32) {
        __syncthreads();
        {
            // K tile: tf32-rounded floats
            float* kd0 = &Ks[frow * KPAD + fc4];
            kd0[0] = __uint_as_float(f2tf32(ka.x));
            kd0[1] = __uint_as_float(f2tf32(ka.y));
            kd0[2] = __uint_as_float(f2tf32(ka.z));
            kd0[3] = __uint_as_float(f2tf32(ka.w));
            float* kd1 = &Ks[(frow + 16) * KPAD + fc4];
            kd1[0] = __uint_as_float(f2tf32(kb4.x));
            kd1[1] = __uint_as_float(f2tf32(kb4.y));
            kd1[2] = __uint_as_float(f2tf32(kb4.z));
            kd1[3] = __uint_as_float(f2tf32(kb4.w));

            // V tile: hi/lo bf16 pairs (k even = row 2vp low half)
            float h0, l0_, h1, l1_;
            uint32_t* vhp = &Vh[vp * VSTR + vcg];
            uint32_t* vlp = &Vl[vp * VSTR + vcg];
            split_bf(va0.x, h0, l0_); split_bf(va1.x, h1, l1_);
            vhp[0] = packbf(h0, h1);  vlp[0] = packbf(l0_, l1_);
            split_bf(va0.y, h0, l0_); split_bf(va1.y, h1, l1_);
            vhp[1] = packbf(h0, h1);  vlp[1] = packbf(l0_, l1_);
            split_bf(va0.z, h0, l0_); split_bf(va1.z, h1, l1_);
            vhp[2] = packbf(h0, h1);  vlp[2] = packbf(l0_, l1_);
            split_bf(va0.w, h0, l0_); split_bf(va1.w, h1, l1_);
            vhp[3] = packbf(h0, h1);  vlp[3] = packbf(l0_, l1_);

            if (tid < 32) Bs[tid] = g_bias[b * T_ + s0 + tid];
        }
        __syncthreads();

        if (s0 + 32 < T_) {
            ka  = *(const float4*)(kRow + (size_t)(s0 + 32) * D_);
            kb4 = *(const float4*)(kRow + (size_t)(s0 + 48) * D_);
            va0 = *(const float4*)(vRow0 + (size_t)(s0 + 32) * D_);
            va1 = *(const float4*)(vRow1 + (size_t)(s0 + 32) * D_);
        }

        // ---- S = Q K^T (tf32 x1) ----
        float sacc[4][4];
#pragma unroll
        for (int nt = 0; nt < 4; nt++)
#pragma unroll
            for (int i = 0; i < 4; i++) sacc[nt][i] = 0.f;
#pragma unroll
        for (int ks = 0; ks < 8; ks++) {
            const int kb = ks * 8;
#pragma unroll
            for (int nt = 0; nt < 4; nt++) {
                const float* kp = &Ks[(nt * 8 + gid) * KPAD + kb + tig];
                uint32_t bf[2];
                bf[0] = __float_as_uint(kp[0]);
                bf[1] = __float_as_uint(kp[4]);
                mma_tf32(sacc[nt], Qr[ks], bf);
            }
        }

        // ---- scale + bias, online softmax ----
        float sv[4][4];
#pragma unroll
        for (int nt = 0; nt < 4; nt++) {
            int c0 = nt * 8 + 2 * tig;
            float bb0 = Bs[c0], bb1 = Bs[c0 + 1];
            sv[nt][0] = sacc[nt][0] * SCALE_ + bb0;
            sv[nt][1] = sacc[nt][1] * SCALE_ + bb1;
            sv[nt][2] = sacc[nt][2] * SCALE_ + bb0;
            sv[nt][3] = sacc[nt][3] * SCALE_ + bb1;
        }
        float mx0 = fmaxf(fmaxf(sv[0][0], sv[0][1]), fmaxf(sv[1][0], sv[1][1]));
        mx0 = fmaxf(mx0, fmaxf(fmaxf(sv[2][0], sv[2][1]), fmaxf(sv[3][0], sv[3][1])));
        float mx1 = fmaxf(fmaxf(sv[0][2], sv[0][3]), fmaxf(sv[1][2], sv[1][3]));
        mx1 = fmaxf(mx1, fmaxf(fmaxf(sv[2][2], sv[2][3]), fmaxf(sv[3][2], sv[3][3])));
        mx0 = fmaxf(mx0, __shfl_xor_sync(0xffffffffu, mx0, 1));
        mx0 = fmaxf(mx0, __shfl_xor_sync(0xffffffffu, mx0, 2));
        mx1 = fmaxf(mx1, __shfl_xor_sync(0xffffffffu, mx1, 1));
        mx1 = fmaxf(mx1, __shfl_xor_sync(0xffffffffu, mx1, 2));

        float m0n = fmaxf(m0, mx0), m1n = fmaxf(m1, mx1);
        float c0f = __expf(m0 - m0n), c1f = __expf(m1 - m1n);
        m0 = m0n; m1 = m1n;

        float rs0 = 0.f, rs1 = 0.f;
#pragma unroll
        for (int nt = 0; nt < 4; nt++) {
            float p0 = __expf(sv[nt][0] - m0n);
            float p1 = __expf(sv[nt][1] - m0n);
            float p2 = __expf(sv[nt][2] - m1n);
            float p3 = __expf(sv[nt][3] - m1n);
            rs0 += p0 + p1; rs1 += p2 + p3;
            float h0, l0_, h1, l1_;
            int pi = nt * 4 + tig;
            split_bf(p0, h0, l0_); split_bf(p1, h1, l1_);
            Ph[wid][gid * PSTR + pi] = packbf(h0, h1);
            Pl[wid][gid * PSTR + pi] = packbf(l0_, l1_);
            split_bf(p2, h0, l0_); split_bf(p3, h1, l1_);
            Ph[wid][(gid + 8) * PSTR + pi] = packbf(h0, h1);
            Pl[wid][(gid + 8) * PSTR + pi] = packbf(l0_, l1_);
        }
        rs0 += __shfl_xor_sync(0xffffffffu, rs0, 1);
        rs0 += __shfl_xor_sync(0xffffffffu, rs0, 2);
        rs1 += __shfl_xor_sync(0xffffffffu, rs1, 1);
        rs1 += __shfl_xor_sync(0xffffffffu, rs1, 2);
        l0 = l0 * c0f + rs0;
        l1 = l1 * c1f + rs1;
#pragma unroll
        for (int nt = 0; nt < 8; nt++) {
            oacc[nt][0] *= c0f; oacc[nt][1] *= c0f;
            oacc[nt][2] *= c1f; oacc[nt][3] *= c1f;
        }
        __syncwarp();

        // ---- O += P V (bf16 x3, m16n8k16) ----
#pragma unroll
        for (int kk = 0; kk < 2; kk++) {
            uint32_t ah[4], al[4];
            ah[0] = Ph[wid][gid * PSTR + kk * 8 + tig];
            ah[1] = Ph[wid][(gid + 8) * PSTR + kk * 8 + tig];
            ah[2] = Ph[wid][gid * PSTR + kk * 8 + tig + 4];
            ah[3] = Ph[wid][(gid + 8) * PSTR + kk * 8 + tig + 4];
            al[0] = Pl[wid][gid * PSTR + kk * 8 + tig];
            al[1] = Pl[wid][(gid + 8) * PSTR + kk * 8 + tig];
            al[2] = Pl[wid][gid * PSTR + kk * 8 + tig + 4];
            al[3] = Pl[wid][(gid + 8) * PSTR + kk * 8 + tig + 4];
#pragma unroll
            for (int nt = 0; nt < 8; nt++) {
                uint32_t bh[2], bl[2];
                bh[0] = Vh[(kk * 8 + tig) * VSTR + nt * 8 + gid];
                bh[1] = Vh[(kk * 8 + tig + 4) * VSTR + nt * 8 + gid];
                bl[0] = Vl[(kk * 8 + tig) * VSTR + nt * 8 + gid];
                bl[1] = Vl[(kk * 8 + tig + 4) * VSTR + nt * 8 + gid];
                mma_bf16(oacc[nt], ah, bh);
                mma_bf16(oacc[nt], al, bh);
                mma_bf16(oacc[nt], ah, bl);
            }
        }
        __syncwarp();
    }

    // ---- epilogue ----
    float inv0 = 1.f / l0, inv1 = 1.f / l1;
    const int gr0 = t0 + wid * 16 + gid;
    float* o0 = CTX + ((size_t)(b * T_) + gr0) * D_ + h * DK_;
    float* o1 = o0 + 8 * D_;
#pragma unroll
    for (int nt = 0; nt < 8; nt++) {
        int c = nt * 8 + 2 * tig;
        *(float2*)(o0 + c) = make_float2(oacc[nt][0] * inv0, oacc[nt][1] * inv0);
        *(float2*)(o1 + c) = make_float2(oacc[nt][2] * inv1, oacc[nt][3] * inv1);
    }
}

// ---------------- launch ----------------
extern "C" void kernel_launch(void* const* d_in, const int* in_sizes, int n_in,
                              void* d_out, int out_size)
{
    const float* query = (const float*)d_in[0];
    const float* key   = (const float*)d_in[1];
    const float* value = (const float*)d_in[2];
    const void*  mask  = d_in[3];
    const float* Wq = (const float*)d_in[4];  const float* bq = (const float*)d_in[5];
    const float* Wk = (const float*)d_in[6];  const float* bk = (const float*)d_in[7];
    const float* Wv = (const float*)d_in[8];  const float* bv = (const float*)d_in[9];
    const float* Wo = (const float*)d_in[10]; const float* bo = (const float*)d_in[11];

    float *Qb, *Kb, *Vb, *Cb;
    cudaGetSymbolAddress((void**)&Qb, g_Q);
    cudaGetSymbolAddress((void**)&Kb, g_K);
    cudaGetSymbolAddress((void**)&Vb, g_V);
    cudaGetSymbolAddress((void**)&Cb, g_CTX);

    detect_mask_kernel<<<1, 256>>>((const unsigned int*)mask);
    build_bias_kernel<<<(M_ + 255) / 256, 256>>>(mask);

    dim3 gg(D_ / 128, M_ / 64);   // (8, 64)
    gemm_bf16x3_kernel<<<gg, 256>>>(query, Wq, bq, Qb);
    gemm_bf16x3_kernel<<<gg, 256>>>(key,   Wk, bk, Kb);
    gemm_bf16x3_kernel<<<gg, 256>>>(value, Wv, bv, Vb);

    attn_mma_kernel<<<dim3(T_ / 128, H_, B_), 256>>>(Qb, Kb, Vb, Cb);

    gemm_bf16x3_kernel<<<gg, 256>>>(Cb, Wo, bo, (float*)d_out);
}